// round 12
// baseline (speedup 1.0000x reference)
#include <cuda_runtime.h>

#define IMG_H 512
#define IMG_W 512
#define TH 16
#define TW 32
#define HALO 5
#define INW (TW + 2*HALO)   // 42 vertical-result columns
#define SW  (INW + 1)       // 43, odd stride vs 32 banks (conflict-free, proven R5/R9)
#define PLANE (TH*SW)       // 688
#define NBX (IMG_W/TW)      // 16
#define NBY (IMG_H/TH)      // 32
#define NBZ 96
#define NBLOCKS (NBX*NBY*NBZ)  // 49152
#define CHUNK 4
#define NCHUNKS (TH/CHUNK)     // 4
#define VITEMS (INW*NCHUNKS)   // 168 vertical work items
#define NTHREADS 128

typedef unsigned long long ull;

__device__ float  g_partials[NBLOCKS];
__device__ double g_p2[32];

// ---- packed f32x2 helpers (sm_103a FFMA2 path) ----
__device__ __forceinline__ ull pk2(float lo, float hi) {
    ull r; asm("mov.b64 %0, {%1,%2};" : "=l"(r) : "f"(lo), "f"(hi)); return r;
}
__device__ __forceinline__ void upk2(ull v, float& lo, float& hi) {
    asm("mov.b64 {%0,%1}, %2;" : "=f"(lo), "=f"(hi) : "l"(v));
}
__device__ __forceinline__ ull fma2(ull a, ull b, ull c) {
    ull r; asm("fma.rn.f32x2 %0, %1, %2, %3;" : "=l"(r) : "l"(a), "l"(b), "l"(c)); return r;
}
__device__ __forceinline__ ull mul2(ull a, ull b) {
    ull r; asm("mul.rn.f32x2 %0, %1, %2;" : "=l"(r) : "l"(a), "l"(b)); return r;
}

// 4-field SSIM: m1=mu1, m2=mu2, S=E[x^2+y^2], Q=E[xy]
__device__ __forceinline__ float ssim_val4(float m1, float m2, float S, float Q) {
    const float C1 = 1e-4f;
    const float C2 = 9e-4f;
    float mu11 = m1 * m1;
    float mu22 = m2 * m2;
    float mu12 = m1 * m2;
    float num = (2.0f * mu12 + C1) * (2.0f * (Q - mu12) + C2);
    float den = (mu11 + mu22 + C1) * ((S - mu11 - mu22) + C2);
    return __fdividef(num, den);
}

__global__ void ssim_nop() {}

__global__ void __launch_bounds__(NTHREADS, 8)
ssim_main(const float* __restrict__ g1, const float* __restrict__ g2) {
    // Gaussian weights (sigma=1.5), computed offline in double then cast.
    constexpr float W11[11] = {
        0.00102838f, 0.00759876f, 0.03600077f, 0.10936069f, 0.21300552f,
        0.26601172f,
        0.21300552f, 0.10936069f, 0.03600077f, 0.00759876f, 0.00102838f };
    constexpr float W5[5] = {
        0.12007838f, 0.23388074f, 0.29208172f, 0.23388074f, 0.12007838f };

    // 8 scalar planes: [0]=mu1_5 [1]=mu2_5 [2]=s5 [3]=q5
    //                  [4]=mu1_11 [5]=mu2_11 [6]=s11 [7]=q11
    extern __shared__ float vp[];

    const int t = threadIdx.x;
    const int r0 = blockIdx.y * TH;
    const int c0 = blockIdx.x * TW;
    const float* i1 = g1 + (size_t)blockIdx.z * (IMG_H * IMG_W);
    const float* i2 = g2 + (size_t)blockIdx.z * (IMG_H * IMG_W);

    ull W2[11], U2[5];
    #pragma unroll
    for (int i = 0; i < 11; i++) W2[i] = pk2(W11[i], W11[i]);
    #pragma unroll
    for (int i = 0; i < 5; i++)  U2[i] = pk2(W5[i], W5[i]);

    // ---- vertical pass: global -> regs (14-row span) -> scatter -> vp ----
    for (int i = t; i < VITEMS; i += NTHREADS) {
        int chunk = i / INW;          // 0..3
        int vcol  = i - chunk * INW;  // 0..41
        int gc = c0 - HALO + vcol;
        int grb = r0 + CHUNK * chunk - HALO;
        bool colok = (unsigned)gc < IMG_W;

        ull P11[CHUNK], SQ11[CHUNK], P5[CHUNK], SQ5[CHUNK];
        #pragma unroll
        for (int o = 0; o < CHUNK; o++) {
            P11[o] = SQ11[o] = P5[o] = SQ5[o] = 0ULL;
        }
        #pragma unroll
        for (int j = 0; j < CHUNK + 10; j++) {   // 14 input rows
            int gr = grb + j;
            float x = 0.f, y = 0.f;
            if (colok && (unsigned)gr < IMG_H) {
                int gi = gr * IMG_W + gc;
                x = i1[gi];
                y = i2[gi];
            }
            ull p = pk2(x, y);
            float xx, yy;
            upk2(mul2(p, p), xx, yy);
            ull sq = pk2(xx + yy, x * y);        // (s, q)
            #pragma unroll
            for (int o = 0; o < CHUNK; o++) {
                int k = j - o;                   // tap index for output row o
                if (k >= 0 && k < 11) {
                    P11[o]  = fma2(W2[k], p,  P11[o]);
                    SQ11[o] = fma2(W2[k], sq, SQ11[o]);
                }
                if (k >= 3 && k < 8) {
                    P5[o]  = fma2(U2[k-3], p,  P5[o]);
                    SQ5[o] = fma2(U2[k-3], sq, SQ5[o]);
                }
            }
        }
        #pragma unroll
        for (int o = 0; o < CHUNK; o++) {
            int off = (CHUNK * chunk + o) * SW + vcol;
            float lo, hi;
            upk2(P5[o], lo, hi);   vp[0*PLANE + off] = lo; vp[1*PLANE + off] = hi;
            upk2(SQ5[o], lo, hi);  vp[2*PLANE + off] = lo; vp[3*PLANE + off] = hi;
            upk2(P11[o], lo, hi);  vp[4*PLANE + off] = lo; vp[5*PLANE + off] = hi;
            upk2(SQ11[o], lo, hi); vp[6*PLANE + off] = lo; vp[7*PLANE + off] = hi;
        }
    }
    __syncthreads();

    // ---- horizontal pass (4 consecutive output columns per thread) ----
    const int rr = t >> 3;          // 0..15
    const int cc = (t & 7) * 4;     // 0,4,...,28
    const float* b5  = vp + rr * SW + cc;
    const float* b11 = b5 + 4 * PLANE;

    float lsum = 0.f;

    // map (kh=5, kw=11): h11 over v5 planes
    {
        ull aP[4], aSQ[4];
        #pragma unroll
        for (int p = 0; p < 4; p++) { aP[p] = 0ULL; aSQ[p] = 0ULL; }
        #pragma unroll
        for (int dx = 0; dx < 14; dx++) {
            float v0 = b5[dx];
            float v1 = b5[PLANE + dx];
            float v2 = b5[2*PLANE + dx];
            float v3 = b5[3*PLANE + dx];
            ull pP = pk2(v0, v1);
            ull pS = pk2(v2, v3);
            #pragma unroll
            for (int p = 0; p < 4; p++) {
                int k = dx - p;
                if (k >= 0 && k < 11) {
                    aP[p]  = fma2(W2[k], pP, aP[p]);
                    aSQ[p] = fma2(W2[k], pS, aSQ[p]);
                }
            }
        }
        #pragma unroll
        for (int p = 0; p < 4; p++) {
            float m1, m2, S, Q;
            upk2(aP[p], m1, m2); upk2(aSQ[p], S, Q);
            lsum += ssim_val4(m1, m2, S, Q);
        }
    }

    // maps (11,5) via h5 and (11,11) via h11, both over v11 planes
    {
        ull bP[4], bSQ[4], cP[4], cSQ[4];
        #pragma unroll
        for (int p = 0; p < 4; p++) {
            bP[p] = bSQ[p] = cP[p] = cSQ[p] = 0ULL;
        }
        #pragma unroll
        for (int dx = 0; dx < 14; dx++) {
            float v0 = b11[dx];
            float v1 = b11[PLANE + dx];
            float v2 = b11[2*PLANE + dx];
            float v3 = b11[3*PLANE + dx];
            ull pP = pk2(v0, v1);
            ull pS = pk2(v2, v3);
            #pragma unroll
            for (int p = 0; p < 4; p++) {
                int k = dx - p;
                if (k >= 0 && k < 11) {
                    cP[p]  = fma2(W2[k], pP, cP[p]);
                    cSQ[p] = fma2(W2[k], pS, cSQ[p]);
                }
                int m = k - 3;
                if (m >= 0 && m < 5) {
                    bP[p]  = fma2(U2[m], pP, bP[p]);
                    bSQ[p] = fma2(U2[m], pS, bSQ[p]);
                }
            }
        }
        #pragma unroll
        for (int p = 0; p < 4; p++) {
            float m1, m2, S, Q;
            upk2(bP[p], m1, m2); upk2(bSQ[p], S, Q);
            lsum += ssim_val4(m1, m2, S, Q);
            upk2(cP[p], m1, m2); upk2(cSQ[p], S, Q);
            lsum += ssim_val4(m1, m2, S, Q);
        }
    }

    // ---- block reduction -> per-block partial ----
    #pragma unroll
    for (int o = 16; o; o >>= 1) lsum += __shfl_xor_sync(0xffffffffu, lsum, o);
    __shared__ float warp_sums[4];
    if ((t & 31) == 0) warp_sums[t >> 5] = lsum;
    __syncthreads();
    if (t == 0) {
        float s = 0.f;
        #pragma unroll
        for (int w = 0; w < 4; w++) s += warp_sums[w];
        g_partials[(blockIdx.z * NBY + blockIdx.y) * NBX + blockIdx.x] = s;
    }
}

// stage 1: 32 blocks x 256 threads, each block sums 1536 partials
__global__ void ssim_reduce1() {
    int t = threadIdx.x;
    int base = blockIdx.x * 1536;
    double s = 0.0;
    #pragma unroll
    for (int j = 0; j < 6; j++)
        s += (double)g_partials[base + t + j * 256];
    #pragma unroll
    for (int o = 16; o; o >>= 1) s += __shfl_xor_sync(0xffffffffu, s, o);
    __shared__ double ws[8];
    if ((t & 31) == 0) ws[t >> 5] = s;
    __syncthreads();
    if (t == 0) {
        double v = 0.0;
        #pragma unroll
        for (int w = 0; w < 8; w++) v += ws[w];
        g_p2[blockIdx.x] = v;
    }
}

// stage 2: single warp
__global__ void ssim_reduce2(float* __restrict__ out) {
    int t = threadIdx.x;
    double v = g_p2[t];
    #pragma unroll
    for (int o = 16; o; o >>= 1) v += __shfl_xor_sync(0xffffffffu, v, o);
    if (t == 0) out[0] = (float)(v / (3.0 * 25165824.0));  // 3 maps * 32*3*512*512
}

extern "C" void kernel_launch(void* const* d_in, const int* in_sizes, int n_in,
                              void* d_out, int out_size) {
    const float* img1 = (const float*)d_in[0];
    const float* img2 = (const float*)d_in[1];
    constexpr int SMEM_BYTES = 8 * PLANE * (int)sizeof(float); // 22016
    cudaFuncSetAttribute(ssim_main, cudaFuncAttributeMaxDynamicSharedMemorySize, SMEM_BYTES);
    dim3 grid(NBX, NBY, NBZ);
    // 3 nops put ssim_main at global launch index 5 == ncu's -s 5 -c 1 slot
    // (verified R3..R11: profile hit ssim_main).
    ssim_nop<<<1, 32>>>();
    ssim_nop<<<1, 32>>>();
    ssim_nop<<<1, 32>>>();
    ssim_main<<<grid, NTHREADS, SMEM_BYTES>>>(img1, img2);
    ssim_reduce1<<<32, 256>>>();
    ssim_reduce2<<<1, 32>>>((float*)d_out);
}

// round 13
// speedup vs baseline: 1.1109x; 1.1109x over previous
#include <cuda_runtime.h>

#define IMG_H 512
#define IMG_W 512
#define TH 16
#define TW 32
#define HALO 5
#define INW (TW + 2*HALO)   // 42 vertical-result columns
#define SW  (INW + 1)       // 43, odd stride vs 32 banks (conflict-free, proven R5/R9/R11)
#define PLANE (TH*SW)       // 688
#define NBX (IMG_W/TW)      // 16
#define NBY (IMG_H/TH)      // 32
#define NBZ 96
#define NBLOCKS (NBX*NBY*NBZ)  // 49152
#define CHUNK 4
#define NTHREADS 128

typedef unsigned long long ull;

__device__ float  g_partials[NBLOCKS];
__device__ double g_p2[32];

// ---- packed f32x2 helpers (sm_103a FFMA2 path) ----
__device__ __forceinline__ ull pk2(float lo, float hi) {
    ull r; asm("mov.b64 %0, {%1,%2};" : "=l"(r) : "f"(lo), "f"(hi)); return r;
}
__device__ __forceinline__ void upk2(ull v, float& lo, float& hi) {
    asm("mov.b64 {%0,%1}, %2;" : "=f"(lo), "=f"(hi) : "l"(v));
}
__device__ __forceinline__ ull fma2(ull a, ull b, ull c) {
    ull r; asm("fma.rn.f32x2 %0, %1, %2, %3;" : "=l"(r) : "l"(a), "l"(b), "l"(c)); return r;
}
__device__ __forceinline__ ull mul2(ull a, ull b) {
    ull r; asm("mul.rn.f32x2 %0, %1, %2;" : "=l"(r) : "l"(a), "l"(b)); return r;
}

// 4-field SSIM: m1=mu1, m2=mu2, S=E[x^2+y^2], Q=E[xy]
__device__ __forceinline__ float ssim_val4(float m1, float m2, float S, float Q) {
    const float C1 = 1e-4f;
    const float C2 = 9e-4f;
    float mu11 = m1 * m1;
    float mu22 = m2 * m2;
    float mu12 = m1 * m2;
    float num = (2.0f * mu12 + C1) * (2.0f * (Q - mu12) + C2);
    float den = (mu11 + mu22 + C1) * ((S - mu11 - mu22) + C2);
    return __fdividef(num, den);
}

__global__ void ssim_nop() {}

__global__ void __launch_bounds__(NTHREADS, 7)
ssim_main(const float* __restrict__ g1, const float* __restrict__ g2) {
    // Gaussian weights (sigma=1.5), computed offline in double then cast.
    constexpr float W11[11] = {
        0.00102838f, 0.00759876f, 0.03600077f, 0.10936069f, 0.21300552f,
        0.26601172f,
        0.21300552f, 0.10936069f, 0.03600077f, 0.00759876f, 0.00102838f };
    constexpr float W5[5] = {
        0.12007838f, 0.23388074f, 0.29208172f, 0.23388074f, 0.12007838f };

    // 8 scalar planes: [0]=mu1_5 [1]=mu2_5 [2]=s5 [3]=q5
    //                  [4]=mu1_11 [5]=mu2_11 [6]=s11 [7]=q11
    extern __shared__ float vp[];

    const int t = threadIdx.x;
    const int r0 = blockIdx.y * TH;
    const int c0 = blockIdx.x * TW;
    const float* i1 = g1 + (size_t)blockIdx.z * (IMG_H * IMG_W);
    const float* i2 = g2 + (size_t)blockIdx.z * (IMG_H * IMG_W);

    ull W2[11], U2[5];
    #pragma unroll
    for (int i = 0; i < 11; i++) W2[i] = pk2(W11[i], W11[i]);
    #pragma unroll
    for (int i = 0; i < 5; i++)  U2[i] = pk2(W5[i], W5[i]);

    // ---- vertical pass, iter0: every thread one full CHUNK=4 item ----
    // items 0..127 cover chunks 0..2 fully (cols 0..41) + chunk 3 cols 0,1
    {
        int i = t;
        int chunk = i / INW;          // 0..3
        int vcol  = i - chunk * INW;  // 0..41
        int gc = c0 - HALO + vcol;
        int grb = r0 + CHUNK * chunk - HALO;
        bool colok = (unsigned)gc < IMG_W;

        ull P11[CHUNK], SQ11[CHUNK], P5[CHUNK], SQ5[CHUNK];
        #pragma unroll
        for (int o = 0; o < CHUNK; o++) {
            P11[o] = SQ11[o] = P5[o] = SQ5[o] = 0ULL;
        }
        #pragma unroll
        for (int j = 0; j < CHUNK + 10; j++) {   // 14 input rows
            int gr = grb + j;
            float x = 0.f, y = 0.f;
            if (colok && (unsigned)gr < IMG_H) {
                int gi = gr * IMG_W + gc;
                x = i1[gi];
                y = i2[gi];
            }
            ull p = pk2(x, y);
            float xx, yy;
            upk2(mul2(p, p), xx, yy);
            ull sq = pk2(xx + yy, x * y);        // (s, q)
            #pragma unroll
            for (int o = 0; o < CHUNK; o++) {
                int k = j - o;                   // tap index for output row o
                if (k >= 0 && k < 11) {
                    P11[o]  = fma2(W2[k], p,  P11[o]);
                    SQ11[o] = fma2(W2[k], sq, SQ11[o]);
                }
                if (k >= 3 && k < 8) {
                    P5[o]  = fma2(U2[k-3], p,  P5[o]);
                    SQ5[o] = fma2(U2[k-3], sq, SQ5[o]);
                }
            }
        }
        #pragma unroll
        for (int o = 0; o < CHUNK; o++) {
            int off = (CHUNK * chunk + o) * SW + vcol;
            float lo, hi;
            upk2(P5[o], lo, hi);   vp[0*PLANE + off] = lo; vp[1*PLANE + off] = hi;
            upk2(SQ5[o], lo, hi);  vp[2*PLANE + off] = lo; vp[3*PLANE + off] = hi;
            upk2(P11[o], lo, hi);  vp[4*PLANE + off] = lo; vp[5*PLANE + off] = hi;
            upk2(SQ11[o], lo, hi); vp[6*PLANE + off] = lo; vp[7*PLANE + off] = hi;
        }
    }

    // ---- vertical pass, iter1: chunk 3 cols 2..41 as 80 HALF items ----
    // (2 output rows each, 12 input rows; spread over 2.5 warps instead of
    //  1.25 warps doing full double work -> critical path 2.0 -> ~1.5 bodies)
    if (t < 80) {
        int sub  = t / 40;            // 0: rows 12-13, 1: rows 14-15
        int vcol = 2 + (t - sub * 40);
        int gc = c0 - HALO + vcol;
        int grb = r0 + 12 + 2 * sub - HALO;
        bool colok = (unsigned)gc < IMG_W;

        ull P11[2], SQ11[2], P5[2], SQ5[2];
        #pragma unroll
        for (int o = 0; o < 2; o++) {
            P11[o] = SQ11[o] = P5[o] = SQ5[o] = 0ULL;
        }
        #pragma unroll
        for (int j = 0; j < 12; j++) {           // 12 input rows
            int gr = grb + j;
            float x = 0.f, y = 0.f;
            if (colok && (unsigned)gr < IMG_H) {
                int gi = gr * IMG_W + gc;
                x = i1[gi];
                y = i2[gi];
            }
            ull p = pk2(x, y);
            float xx, yy;
            upk2(mul2(p, p), xx, yy);
            ull sq = pk2(xx + yy, x * y);        // (s, q)
            #pragma unroll
            for (int o = 0; o < 2; o++) {
                int k = j - o;
                if (k >= 0 && k < 11) {
                    P11[o]  = fma2(W2[k], p,  P11[o]);
                    SQ11[o] = fma2(W2[k], sq, SQ11[o]);
                }
                if (k >= 3 && k < 8) {
                    P5[o]  = fma2(U2[k-3], p,  P5[o]);
                    SQ5[o] = fma2(U2[k-3], sq, SQ5[o]);
                }
            }
        }
        #pragma unroll
        for (int o = 0; o < 2; o++) {
            int off = (12 + 2 * sub + o) * SW + vcol;
            float lo, hi;
            upk2(P5[o], lo, hi);   vp[0*PLANE + off] = lo; vp[1*PLANE + off] = hi;
            upk2(SQ5[o], lo, hi);  vp[2*PLANE + off] = lo; vp[3*PLANE + off] = hi;
            upk2(P11[o], lo, hi);  vp[4*PLANE + off] = lo; vp[5*PLANE + off] = hi;
            upk2(SQ11[o], lo, hi); vp[6*PLANE + off] = lo; vp[7*PLANE + off] = hi;
        }
    }
    __syncthreads();

    // ---- horizontal pass (4 consecutive output columns per thread) ----
    const int rr = t >> 3;          // 0..15
    const int cc = (t & 7) * 4;     // 0,4,...,28
    const float* b5  = vp + rr * SW + cc;
    const float* b11 = b5 + 4 * PLANE;

    float lsum = 0.f;

    // map (kh=5, kw=11): h11 over v5 planes
    {
        ull aP[4], aSQ[4];
        #pragma unroll
        for (int p = 0; p < 4; p++) { aP[p] = 0ULL; aSQ[p] = 0ULL; }
        #pragma unroll
        for (int dx = 0; dx < 14; dx++) {
            float v0 = b5[dx];
            float v1 = b5[PLANE + dx];
            float v2 = b5[2*PLANE + dx];
            float v3 = b5[3*PLANE + dx];
            ull pP = pk2(v0, v1);
            ull pS = pk2(v2, v3);
            #pragma unroll
            for (int p = 0; p < 4; p++) {
                int k = dx - p;
                if (k >= 0 && k < 11) {
                    aP[p]  = fma2(W2[k], pP, aP[p]);
                    aSQ[p] = fma2(W2[k], pS, aSQ[p]);
                }
            }
        }
        #pragma unroll
        for (int p = 0; p < 4; p++) {
            float m1, m2, S, Q;
            upk2(aP[p], m1, m2); upk2(aSQ[p], S, Q);
            lsum += ssim_val4(m1, m2, S, Q);
        }
    }

    // maps (11,5) via h5 and (11,11) via h11, both over v11 planes
    {
        ull bP[4], bSQ[4], cP[4], cSQ[4];
        #pragma unroll
        for (int p = 0; p < 4; p++) {
            bP[p] = bSQ[p] = cP[p] = cSQ[p] = 0ULL;
        }
        #pragma unroll
        for (int dx = 0; dx < 14; dx++) {
            float v0 = b11[dx];
            float v1 = b11[PLANE + dx];
            float v2 = b11[2*PLANE + dx];
            float v3 = b11[3*PLANE + dx];
            ull pP = pk2(v0, v1);
            ull pS = pk2(v2, v3);
            #pragma unroll
            for (int p = 0; p < 4; p++) {
                int k = dx - p;
                if (k >= 0 && k < 11) {
                    cP[p]  = fma2(W2[k], pP, cP[p]);
                    cSQ[p] = fma2(W2[k], pS, cSQ[p]);
                }
                int m = k - 3;
                if (m >= 0 && m < 5) {
                    bP[p]  = fma2(U2[m], pP, bP[p]);
                    bSQ[p] = fma2(U2[m], pS, bSQ[p]);
                }
            }
        }
        #pragma unroll
        for (int p = 0; p < 4; p++) {
            float m1, m2, S, Q;
            upk2(bP[p], m1, m2); upk2(bSQ[p], S, Q);
            lsum += ssim_val4(m1, m2, S, Q);
            upk2(cP[p], m1, m2); upk2(cSQ[p], S, Q);
            lsum += ssim_val4(m1, m2, S, Q);
        }
    }

    // ---- block reduction -> per-block partial ----
    #pragma unroll
    for (int o = 16; o; o >>= 1) lsum += __shfl_xor_sync(0xffffffffu, lsum, o);
    __shared__ float warp_sums[4];
    if ((t & 31) == 0) warp_sums[t >> 5] = lsum;
    __syncthreads();
    if (t == 0) {
        float s = 0.f;
        #pragma unroll
        for (int w = 0; w < 4; w++) s += warp_sums[w];
        g_partials[(blockIdx.z * NBY + blockIdx.y) * NBX + blockIdx.x] = s;
    }
}

// stage 1: 32 blocks x 256 threads, each block sums 1536 partials
__global__ void ssim_reduce1() {
    int t = threadIdx.x;
    int base = blockIdx.x * 1536;
    double s = 0.0;
    #pragma unroll
    for (int j = 0; j < 6; j++)
        s += (double)g_partials[base + t + j * 256];
    #pragma unroll
    for (int o = 16; o; o >>= 1) s += __shfl_xor_sync(0xffffffffu, s, o);
    __shared__ double ws[8];
    if ((t & 31) == 0) ws[t >> 5] = s;
    __syncthreads();
    if (t == 0) {
        double v = 0.0;
        #pragma unroll
        for (int w = 0; w < 8; w++) v += ws[w];
        g_p2[blockIdx.x] = v;
    }
}

// stage 2: single warp
__global__ void ssim_reduce2(float* __restrict__ out) {
    int t = threadIdx.x;
    double v = g_p2[t];
    #pragma unroll
    for (int o = 16; o; o >>= 1) v += __shfl_xor_sync(0xffffffffu, v, o);
    if (t == 0) out[0] = (float)(v / (3.0 * 25165824.0));  // 3 maps * 32*3*512*512
}

extern "C" void kernel_launch(void* const* d_in, const int* in_sizes, int n_in,
                              void* d_out, int out_size) {
    const float* img1 = (const float*)d_in[0];
    const float* img2 = (const float*)d_in[1];
    constexpr int SMEM_BYTES = 8 * PLANE * (int)sizeof(float); // 22016
    cudaFuncSetAttribute(ssim_main, cudaFuncAttributeMaxDynamicSharedMemorySize, SMEM_BYTES);
    dim3 grid(NBX, NBY, NBZ);
    // 3 nops put ssim_main at global launch index 5 == ncu's -s 5 -c 1 slot
    // (verified R3..R12: profile hit ssim_main).
    ssim_nop<<<1, 32>>>();
    ssim_nop<<<1, 32>>>();
    ssim_nop<<<1, 32>>>();
    ssim_main<<<grid, NTHREADS, SMEM_BYTES>>>(img1, img2);
    ssim_reduce1<<<32, 256>>>();
    ssim_reduce2<<<1, 32>>>((float*)d_out);
}

// round 14
// speedup vs baseline: 1.1893x; 1.0706x over previous
#include <cuda_runtime.h>

#define IMG_H 512
#define IMG_W 512
#define TH 16
#define TW 32
#define HALO 5
#define INW (TW + 2*HALO)   // 42 vertical-result columns
#define SW  (INW + 1)       // 43, odd stride vs 32 banks (conflict-free, proven)
#define PLANE (TH*SW)       // 688
#define NBX (IMG_W/TW)      // 16
#define NBY (IMG_H/TH)      // 32
#define NBZ 96
#define NBLOCKS (NBX*NBY*NBZ)  // 49152
#define CHUNK 4
#define NTHREADS 128

// W5[m] == ALPHA * W11[m+3]  (same Gaussian core, different normalization)
#define ALPHA 1.0980034f

typedef unsigned long long ull;

__device__ float  g_partials[NBLOCKS];
__device__ double g_p2[32];

// ---- packed f32x2 helpers (sm_103a FFMA2 path) ----
__device__ __forceinline__ ull pk2(float lo, float hi) {
    ull r; asm("mov.b64 %0, {%1,%2};" : "=l"(r) : "f"(lo), "f"(hi)); return r;
}
__device__ __forceinline__ void upk2(ull v, float& lo, float& hi) {
    asm("mov.b64 {%0,%1}, %2;" : "=f"(lo), "=f"(hi) : "l"(v));
}
__device__ __forceinline__ ull fma2(ull a, ull b, ull c) {
    ull r; asm("fma.rn.f32x2 %0, %1, %2, %3;" : "=l"(r) : "l"(a), "l"(b), "l"(c)); return r;
}
__device__ __forceinline__ ull mul2(ull a, ull b) {
    ull r; asm("mul.rn.f32x2 %0, %1, %2;" : "=l"(r) : "l"(a), "l"(b)); return r;
}
__device__ __forceinline__ ull add2(ull a, ull b) {
    ull r; asm("add.rn.f32x2 %0, %1, %2;" : "=l"(r) : "l"(a), "l"(b)); return r;
}

// 4-field SSIM: m1=mu1, m2=mu2, S=E[x^2+y^2], Q=E[xy]
__device__ __forceinline__ float ssim_val4(float m1, float m2, float S, float Q) {
    const float C1 = 1e-4f;
    const float C2 = 9e-4f;
    float mu11 = m1 * m1;
    float mu22 = m2 * m2;
    float mu12 = m1 * m2;
    float num = (2.0f * mu12 + C1) * (2.0f * (Q - mu12) + C2);
    float den = (mu11 + mu22 + C1) * ((S - mu11 - mu22) + C2);
    return __fdividef(num, den);
}

__global__ void ssim_nop() {}

__global__ void __launch_bounds__(NTHREADS, 7)
ssim_main(const float* __restrict__ g1, const float* __restrict__ g2) {
    // Gaussian weights (sigma=1.5), computed offline in double then cast.
    constexpr float W11[11] = {
        0.00102838f, 0.00759876f, 0.03600077f, 0.10936069f, 0.21300552f,
        0.26601172f,
        0.21300552f, 0.10936069f, 0.03600077f, 0.00759876f, 0.00102838f };

    // 8 scalar planes: [0]=mu1_5 [1]=mu2_5 [2]=s5 [3]=q5
    //                  [4]=mu1_11 [5]=mu2_11 [6]=s11 [7]=q11
    extern __shared__ float vp[];

    const int t = threadIdx.x;
    const int r0 = blockIdx.y * TH;
    const int c0 = blockIdx.x * TW;
    const float* i1 = g1 + (size_t)blockIdx.z * (IMG_H * IMG_W);
    const float* i2 = g2 + (size_t)blockIdx.z * (IMG_H * IMG_W);

    ull W2[11];
    #pragma unroll
    for (int i = 0; i < 11; i++) W2[i] = pk2(W11[i], W11[i]);
    const ull alpha2 = pk2(ALPHA, ALPHA);

    // ---- vertical pass, iter0: every thread one full CHUNK=4 item ----
    // core = taps k in [3,8) of the 11-window; wing = remaining 6 taps.
    // conv11 = core + wing; conv5 = ALPHA * core (shared Gaussian core).
    {
        int i = t;
        int chunk = i / INW;          // 0..3
        int vcol  = i - chunk * INW;  // 0..41
        int gc = c0 - HALO + vcol;
        int grb = r0 + CHUNK * chunk - HALO;
        bool colok = (unsigned)gc < IMG_W;

        ull CP[CHUNK], CSQ[CHUNK], GP[CHUNK], GSQ[CHUNK];  // core / wing
        #pragma unroll
        for (int o = 0; o < CHUNK; o++) {
            CP[o] = CSQ[o] = GP[o] = GSQ[o] = 0ULL;
        }
        #pragma unroll
        for (int j = 0; j < CHUNK + 10; j++) {   // 14 input rows
            int gr = grb + j;
            float x = 0.f, y = 0.f;
            if (colok && (unsigned)gr < IMG_H) {
                int gi = gr * IMG_W + gc;
                x = i1[gi];
                y = i2[gi];
            }
            ull p = pk2(x, y);
            float xx, yy;
            upk2(mul2(p, p), xx, yy);
            ull sq = pk2(xx + yy, x * y);        // (s, q)
            #pragma unroll
            for (int o = 0; o < CHUNK; o++) {
                int k = j - o;                   // tap index for output row o
                if (k >= 3 && k < 8) {
                    CP[o]  = fma2(W2[k], p,  CP[o]);
                    CSQ[o] = fma2(W2[k], sq, CSQ[o]);
                } else if (k >= 0 && k < 11) {
                    GP[o]  = fma2(W2[k], p,  GP[o]);
                    GSQ[o] = fma2(W2[k], sq, GSQ[o]);
                }
            }
        }
        #pragma unroll
        for (int o = 0; o < CHUNK; o++) {
            int off = (CHUNK * chunk + o) * SW + vcol;
            float lo, hi;
            upk2(mul2(alpha2, CP[o]), lo, hi);   // conv5 P
            vp[0*PLANE + off] = lo; vp[1*PLANE + off] = hi;
            upk2(mul2(alpha2, CSQ[o]), lo, hi);  // conv5 SQ
            vp[2*PLANE + off] = lo; vp[3*PLANE + off] = hi;
            upk2(add2(CP[o], GP[o]), lo, hi);    // conv11 P
            vp[4*PLANE + off] = lo; vp[5*PLANE + off] = hi;
            upk2(add2(CSQ[o], GSQ[o]), lo, hi);  // conv11 SQ
            vp[6*PLANE + off] = lo; vp[7*PLANE + off] = hi;
        }
    }

    // ---- vertical pass, iter1: chunk 3 cols 2..41 as 80 HALF items ----
    if (t < 80) {
        int sub  = t / 40;            // 0: rows 12-13, 1: rows 14-15
        int vcol = 2 + (t - sub * 40);
        int gc = c0 - HALO + vcol;
        int grb = r0 + 12 + 2 * sub - HALO;
        bool colok = (unsigned)gc < IMG_W;

        ull CP[2], CSQ[2], GP[2], GSQ[2];
        #pragma unroll
        for (int o = 0; o < 2; o++) {
            CP[o] = CSQ[o] = GP[o] = GSQ[o] = 0ULL;
        }
        #pragma unroll
        for (int j = 0; j < 12; j++) {           // 12 input rows
            int gr = grb + j;
            float x = 0.f, y = 0.f;
            if (colok && (unsigned)gr < IMG_H) {
                int gi = gr * IMG_W + gc;
                x = i1[gi];
                y = i2[gi];
            }
            ull p = pk2(x, y);
            float xx, yy;
            upk2(mul2(p, p), xx, yy);
            ull sq = pk2(xx + yy, x * y);        // (s, q)
            #pragma unroll
            for (int o = 0; o < 2; o++) {
                int k = j - o;
                if (k >= 3 && k < 8) {
                    CP[o]  = fma2(W2[k], p,  CP[o]);
                    CSQ[o] = fma2(W2[k], sq, CSQ[o]);
                } else if (k >= 0 && k < 11) {
                    GP[o]  = fma2(W2[k], p,  GP[o]);
                    GSQ[o] = fma2(W2[k], sq, GSQ[o]);
                }
            }
        }
        #pragma unroll
        for (int o = 0; o < 2; o++) {
            int off = (12 + 2 * sub + o) * SW + vcol;
            float lo, hi;
            upk2(mul2(alpha2, CP[o]), lo, hi);
            vp[0*PLANE + off] = lo; vp[1*PLANE + off] = hi;
            upk2(mul2(alpha2, CSQ[o]), lo, hi);
            vp[2*PLANE + off] = lo; vp[3*PLANE + off] = hi;
            upk2(add2(CP[o], GP[o]), lo, hi);
            vp[4*PLANE + off] = lo; vp[5*PLANE + off] = hi;
            upk2(add2(CSQ[o], GSQ[o]), lo, hi);
            vp[6*PLANE + off] = lo; vp[7*PLANE + off] = hi;
        }
    }
    __syncthreads();

    // ---- horizontal pass (4 consecutive output columns per thread) ----
    const int rr = t >> 3;          // 0..15
    const int cc = (t & 7) * 4;     // 0,4,...,28
    const float* b5  = vp + rr * SW + cc;
    const float* b11 = b5 + 4 * PLANE;

    float lsum = 0.f;

    // map (kh=5, kw=11): h11 over v5 planes
    {
        ull aP[4], aSQ[4];
        #pragma unroll
        for (int p = 0; p < 4; p++) { aP[p] = 0ULL; aSQ[p] = 0ULL; }
        #pragma unroll
        for (int dx = 0; dx < 14; dx++) {
            float v0 = b5[dx];
            float v1 = b5[PLANE + dx];
            float v2 = b5[2*PLANE + dx];
            float v3 = b5[3*PLANE + dx];
            ull pP = pk2(v0, v1);
            ull pS = pk2(v2, v3);
            #pragma unroll
            for (int p = 0; p < 4; p++) {
                int k = dx - p;
                if (k >= 0 && k < 11) {
                    aP[p]  = fma2(W2[k], pP, aP[p]);
                    aSQ[p] = fma2(W2[k], pS, aSQ[p]);
                }
            }
        }
        #pragma unroll
        for (int p = 0; p < 4; p++) {
            float m1, m2, S, Q;
            upk2(aP[p], m1, m2); upk2(aSQ[p], S, Q);
            lsum += ssim_val4(m1, m2, S, Q);
        }
    }

    // maps (11,5) and (11,11) on v11 planes via shared core:
    //   C (h11) = core + wing;  B (h5) = ALPHA * core
    {
        ull cP[4], cSQ[4], gP[4], gSQ[4];
        #pragma unroll
        for (int p = 0; p < 4; p++) {
            cP[p] = cSQ[p] = gP[p] = gSQ[p] = 0ULL;
        }
        #pragma unroll
        for (int dx = 0; dx < 14; dx++) {
            float v0 = b11[dx];
            float v1 = b11[PLANE + dx];
            float v2 = b11[2*PLANE + dx];
            float v3 = b11[3*PLANE + dx];
            ull pP = pk2(v0, v1);
            ull pS = pk2(v2, v3);
            #pragma unroll
            for (int p = 0; p < 4; p++) {
                int k = dx - p;
                if (k >= 3 && k < 8) {
                    cP[p]  = fma2(W2[k], pP, cP[p]);
                    cSQ[p] = fma2(W2[k], pS, cSQ[p]);
                } else if (k >= 0 && k < 11) {
                    gP[p]  = fma2(W2[k], pP, gP[p]);
                    gSQ[p] = fma2(W2[k], pS, gSQ[p]);
                }
            }
        }
        #pragma unroll
        for (int p = 0; p < 4; p++) {
            float m1, m2, S, Q;
            // map B = ALPHA * core
            upk2(mul2(alpha2, cP[p]), m1, m2);
            upk2(mul2(alpha2, cSQ[p]), S, Q);
            lsum += ssim_val4(m1, m2, S, Q);
            // map C = core + wing
            upk2(add2(cP[p], gP[p]), m1, m2);
            upk2(add2(cSQ[p], gSQ[p]), S, Q);
            lsum += ssim_val4(m1, m2, S, Q);
        }
    }

    // ---- block reduction -> per-block partial ----
    #pragma unroll
    for (int o = 16; o; o >>= 1) lsum += __shfl_xor_sync(0xffffffffu, lsum, o);
    __shared__ float warp_sums[4];
    if ((t & 31) == 0) warp_sums[t >> 5] = lsum;
    __syncthreads();
    if (t == 0) {
        float s = 0.f;
        #pragma unroll
        for (int w = 0; w < 4; w++) s += warp_sums[w];
        g_partials[(blockIdx.z * NBY + blockIdx.y) * NBX + blockIdx.x] = s;
    }
}

// stage 1: 32 blocks x 256 threads, each block sums 1536 partials
__global__ void ssim_reduce1() {
    int t = threadIdx.x;
    int base = blockIdx.x * 1536;
    double s = 0.0;
    #pragma unroll
    for (int j = 0; j < 6; j++)
        s += (double)g_partials[base + t + j * 256];
    #pragma unroll
    for (int o = 16; o; o >>= 1) s += __shfl_xor_sync(0xffffffffu, s, o);
    __shared__ double ws[8];
    if ((t & 31) == 0) ws[t >> 5] = s;
    __syncthreads();
    if (t == 0) {
        double v = 0.0;
        #pragma unroll
        for (int w = 0; w < 8; w++) v += ws[w];
        g_p2[blockIdx.x] = v;
    }
}

// stage 2: single warp
__global__ void ssim_reduce2(float* __restrict__ out) {
    int t = threadIdx.x;
    double v = g_p2[t];
    #pragma unroll
    for (int o = 16; o; o >>= 1) v += __shfl_xor_sync(0xffffffffu, v, o);
    if (t == 0) out[0] = (float)(v / (3.0 * 25165824.0));  // 3 maps * 32*3*512*512
}

extern "C" void kernel_launch(void* const* d_in, const int* in_sizes, int n_in,
                              void* d_out, int out_size) {
    const float* img1 = (const float*)d_in[0];
    const float* img2 = (const float*)d_in[1];
    constexpr int SMEM_BYTES = 8 * PLANE * (int)sizeof(float); // 22016
    cudaFuncSetAttribute(ssim_main, cudaFuncAttributeMaxDynamicSharedMemorySize, SMEM_BYTES);
    dim3 grid(NBX, NBY, NBZ);
    // 3 nops put ssim_main at global launch index 5 == ncu's -s 5 -c 1 slot
    // (verified R3..R13: profile hit ssim_main).
    ssim_nop<<<1, 32>>>();
    ssim_nop<<<1, 32>>>();
    ssim_nop<<<1, 32>>>();
    ssim_main<<<grid, NTHREADS, SMEM_BYTES>>>(img1, img2);
    ssim_reduce1<<<32, 256>>>();
    ssim_reduce2<<<1, 32>>>((float*)d_out);
}

// round 15
// speedup vs baseline: 1.1948x; 1.0046x over previous
#include <cuda_runtime.h>

#define IMG_H 512
#define IMG_W 512
#define TH 16
#define TW 32
#define HALO 5
#define INW (TW + 2*HALO)   // 42 vertical-result columns
#define SW  (INW + 1)       // 43, odd stride vs 32 banks (conflict-free, proven)
#define PLANE (TH*SW)       // 688
#define NBX (IMG_W/TW)      // 16
#define NBY (IMG_H/TH)      // 32
#define NBZ 96
#define NBLOCKS (NBX*NBY*NBZ)  // 49152
#define CHUNK 4
#define NTHREADS 128
#define RBLOCKS 192            // 192 * 256 == NBLOCKS

// W5[m] == ALPHA * W11[m+3]  (same Gaussian core, different normalization)
#define ALPHA 1.0980034f

typedef unsigned long long ull;

__device__ float  g_partials[NBLOCKS];
__device__ double g_p2d[RBLOCKS];
__device__ unsigned int g_sem = 0;

// ---- packed f32x2 helpers (sm_103a FFMA2 path) ----
__device__ __forceinline__ ull pk2(float lo, float hi) {
    ull r; asm("mov.b64 %0, {%1,%2};" : "=l"(r) : "f"(lo), "f"(hi)); return r;
}
__device__ __forceinline__ void upk2(ull v, float& lo, float& hi) {
    asm("mov.b64 {%0,%1}, %2;" : "=f"(lo), "=f"(hi) : "l"(v));
}
__device__ __forceinline__ ull fma2(ull a, ull b, ull c) {
    ull r; asm("fma.rn.f32x2 %0, %1, %2, %3;" : "=l"(r) : "l"(a), "l"(b), "l"(c)); return r;
}
__device__ __forceinline__ ull mul2(ull a, ull b) {
    ull r; asm("mul.rn.f32x2 %0, %1, %2;" : "=l"(r) : "l"(a), "l"(b)); return r;
}
__device__ __forceinline__ ull add2(ull a, ull b) {
    ull r; asm("add.rn.f32x2 %0, %1, %2;" : "=l"(r) : "l"(a), "l"(b)); return r;
}

// 4-field SSIM: m1=mu1, m2=mu2, S=E[x^2+y^2], Q=E[xy]
__device__ __forceinline__ float ssim_val4(float m1, float m2, float S, float Q) {
    const float C1 = 1e-4f;
    const float C2 = 9e-4f;
    float mu11 = m1 * m1;
    float mu22 = m2 * m2;
    float mu12 = m1 * m2;
    float num = (2.0f * mu12 + C1) * (2.0f * (Q - mu12) + C2);
    float den = (mu11 + mu22 + C1) * ((S - mu11 - mu22) + C2);
    return __fdividef(num, den);
}

__global__ void ssim_nop() {}

__global__ void __launch_bounds__(NTHREADS, 7)
ssim_main(const float* __restrict__ g1, const float* __restrict__ g2) {
    // Gaussian weights (sigma=1.5), computed offline in double then cast.
    constexpr float W11[11] = {
        0.00102838f, 0.00759876f, 0.03600077f, 0.10936069f, 0.21300552f,
        0.26601172f,
        0.21300552f, 0.10936069f, 0.03600077f, 0.00759876f, 0.00102838f };

    // 8 scalar planes: [0]=mu1_5 [1]=mu2_5 [2]=s5 [3]=q5
    //                  [4]=mu1_11 [5]=mu2_11 [6]=s11 [7]=q11
    extern __shared__ float vp[];

    const int t = threadIdx.x;
    const int r0 = blockIdx.y * TH;
    const int c0 = blockIdx.x * TW;
    const float* i1 = g1 + (size_t)blockIdx.z * (IMG_H * IMG_W);
    const float* i2 = g2 + (size_t)blockIdx.z * (IMG_H * IMG_W);

    ull W2[11];
    #pragma unroll
    for (int i = 0; i < 11; i++) W2[i] = pk2(W11[i], W11[i]);
    const ull alpha2 = pk2(ALPHA, ALPHA);

    // ---- vertical pass, iter0: every thread one full CHUNK=4 item ----
    // core = taps k in [3,8) of the 11-window; wing = remaining 6 taps.
    // conv11 = core + wing; conv5 = ALPHA * core (shared Gaussian core).
    {
        int i = t;
        int chunk = i / INW;          // 0..3
        int vcol  = i - chunk * INW;  // 0..41
        int gc = c0 - HALO + vcol;
        int grb = r0 + CHUNK * chunk - HALO;
        bool colok = (unsigned)gc < IMG_W;

        ull CP[CHUNK], CSQ[CHUNK], GP[CHUNK], GSQ[CHUNK];  // core / wing
        #pragma unroll
        for (int o = 0; o < CHUNK; o++) {
            CP[o] = CSQ[o] = GP[o] = GSQ[o] = 0ULL;
        }
        #pragma unroll
        for (int j = 0; j < CHUNK + 10; j++) {   // 14 input rows
            int gr = grb + j;
            float x = 0.f, y = 0.f;
            if (colok && (unsigned)gr < IMG_H) {
                int gi = gr * IMG_W + gc;
                x = i1[gi];
                y = i2[gi];
            }
            ull p = pk2(x, y);
            float xx, yy;
            upk2(mul2(p, p), xx, yy);
            ull sq = pk2(xx + yy, x * y);        // (s, q)
            #pragma unroll
            for (int o = 0; o < CHUNK; o++) {
                int k = j - o;                   // tap index for output row o
                if (k >= 3 && k < 8) {
                    CP[o]  = fma2(W2[k], p,  CP[o]);
                    CSQ[o] = fma2(W2[k], sq, CSQ[o]);
                } else if (k >= 0 && k < 11) {
                    GP[o]  = fma2(W2[k], p,  GP[o]);
                    GSQ[o] = fma2(W2[k], sq, GSQ[o]);
                }
            }
        }
        #pragma unroll
        for (int o = 0; o < CHUNK; o++) {
            int off = (CHUNK * chunk + o) * SW + vcol;
            float lo, hi;
            upk2(mul2(alpha2, CP[o]), lo, hi);   // conv5 P
            vp[0*PLANE + off] = lo; vp[1*PLANE + off] = hi;
            upk2(mul2(alpha2, CSQ[o]), lo, hi);  // conv5 SQ
            vp[2*PLANE + off] = lo; vp[3*PLANE + off] = hi;
            upk2(add2(CP[o], GP[o]), lo, hi);    // conv11 P
            vp[4*PLANE + off] = lo; vp[5*PLANE + off] = hi;
            upk2(add2(CSQ[o], GSQ[o]), lo, hi);  // conv11 SQ
            vp[6*PLANE + off] = lo; vp[7*PLANE + off] = hi;
        }
    }

    // ---- vertical pass, iter1: chunk 3 cols 2..41 as 80 HALF items ----
    if (t < 80) {
        int sub  = t / 40;            // 0: rows 12-13, 1: rows 14-15
        int vcol = 2 + (t - sub * 40);
        int gc = c0 - HALO + vcol;
        int grb = r0 + 12 + 2 * sub - HALO;
        bool colok = (unsigned)gc < IMG_W;

        ull CP[2], CSQ[2], GP[2], GSQ[2];
        #pragma unroll
        for (int o = 0; o < 2; o++) {
            CP[o] = CSQ[o] = GP[o] = GSQ[o] = 0ULL;
        }
        #pragma unroll
        for (int j = 0; j < 12; j++) {           // 12 input rows
            int gr = grb + j;
            float x = 0.f, y = 0.f;
            if (colok && (unsigned)gr < IMG_H) {
                int gi = gr * IMG_W + gc;
                x = i1[gi];
                y = i2[gi];
            }
            ull p = pk2(x, y);
            float xx, yy;
            upk2(mul2(p, p), xx, yy);
            ull sq = pk2(xx + yy, x * y);        // (s, q)
            #pragma unroll
            for (int o = 0; o < 2; o++) {
                int k = j - o;
                if (k >= 3 && k < 8) {
                    CP[o]  = fma2(W2[k], p,  CP[o]);
                    CSQ[o] = fma2(W2[k], sq, CSQ[o]);
                } else if (k >= 0 && k < 11) {
                    GP[o]  = fma2(W2[k], p,  GP[o]);
                    GSQ[o] = fma2(W2[k], sq, GSQ[o]);
                }
            }
        }
        #pragma unroll
        for (int o = 0; o < 2; o++) {
            int off = (12 + 2 * sub + o) * SW + vcol;
            float lo, hi;
            upk2(mul2(alpha2, CP[o]), lo, hi);
            vp[0*PLANE + off] = lo; vp[1*PLANE + off] = hi;
            upk2(mul2(alpha2, CSQ[o]), lo, hi);
            vp[2*PLANE + off] = lo; vp[3*PLANE + off] = hi;
            upk2(add2(CP[o], GP[o]), lo, hi);
            vp[4*PLANE + off] = lo; vp[5*PLANE + off] = hi;
            upk2(add2(CSQ[o], GSQ[o]), lo, hi);
            vp[6*PLANE + off] = lo; vp[7*PLANE + off] = hi;
        }
    }
    __syncthreads();

    // ---- horizontal pass (4 consecutive output columns per thread) ----
    const int rr = t >> 3;          // 0..15
    const int cc = (t & 7) * 4;     // 0,4,...,28
    const float* b5  = vp + rr * SW + cc;
    const float* b11 = b5 + 4 * PLANE;

    float lsum = 0.f;

    // map (kh=5, kw=11): h11 over v5 planes
    {
        ull aP[4], aSQ[4];
        #pragma unroll
        for (int p = 0; p < 4; p++) { aP[p] = 0ULL; aSQ[p] = 0ULL; }
        #pragma unroll
        for (int dx = 0; dx < 14; dx++) {
            float v0 = b5[dx];
            float v1 = b5[PLANE + dx];
            float v2 = b5[2*PLANE + dx];
            float v3 = b5[3*PLANE + dx];
            ull pP = pk2(v0, v1);
            ull pS = pk2(v2, v3);
            #pragma unroll
            for (int p = 0; p < 4; p++) {
                int k = dx - p;
                if (k >= 0 && k < 11) {
                    aP[p]  = fma2(W2[k], pP, aP[p]);
                    aSQ[p] = fma2(W2[k], pS, aSQ[p]);
                }
            }
        }
        #pragma unroll
        for (int p = 0; p < 4; p++) {
            float m1, m2, S, Q;
            upk2(aP[p], m1, m2); upk2(aSQ[p], S, Q);
            lsum += ssim_val4(m1, m2, S, Q);
        }
    }

    // maps (11,5) and (11,11) on v11 planes via shared core:
    //   C (h11) = core + wing;  B (h5) = ALPHA * core
    {
        ull cP[4], cSQ[4], gP[4], gSQ[4];
        #pragma unroll
        for (int p = 0; p < 4; p++) {
            cP[p] = cSQ[p] = gP[p] = gSQ[p] = 0ULL;
        }
        #pragma unroll
        for (int dx = 0; dx < 14; dx++) {
            float v0 = b11[dx];
            float v1 = b11[PLANE + dx];
            float v2 = b11[2*PLANE + dx];
            float v3 = b11[3*PLANE + dx];
            ull pP = pk2(v0, v1);
            ull pS = pk2(v2, v3);
            #pragma unroll
            for (int p = 0; p < 4; p++) {
                int k = dx - p;
                if (k >= 3 && k < 8) {
                    cP[p]  = fma2(W2[k], pP, cP[p]);
                    cSQ[p] = fma2(W2[k], pS, cSQ[p]);
                } else if (k >= 0 && k < 11) {
                    gP[p]  = fma2(W2[k], pP, gP[p]);
                    gSQ[p] = fma2(W2[k], pS, gSQ[p]);
                }
            }
        }
        #pragma unroll
        for (int p = 0; p < 4; p++) {
            float m1, m2, S, Q;
            // map B = ALPHA * core
            upk2(mul2(alpha2, cP[p]), m1, m2);
            upk2(mul2(alpha2, cSQ[p]), S, Q);
            lsum += ssim_val4(m1, m2, S, Q);
            // map C = core + wing
            upk2(add2(cP[p], gP[p]), m1, m2);
            upk2(add2(cSQ[p], gSQ[p]), S, Q);
            lsum += ssim_val4(m1, m2, S, Q);
        }
    }

    // ---- block reduction -> per-block partial ----
    #pragma unroll
    for (int o = 16; o; o >>= 1) lsum += __shfl_xor_sync(0xffffffffu, lsum, o);
    __shared__ float warp_sums[4];
    if ((t & 31) == 0) warp_sums[t >> 5] = lsum;
    __syncthreads();
    if (t == 0) {
        float s = 0.f;
        #pragma unroll
        for (int w = 0; w < 4; w++) s += warp_sums[w];
        g_partials[(blockIdx.z * NBY + blockIdx.y) * NBX + blockIdx.x] = s;
    }
}

// Fused reduction: 192 blocks x 256 threads (1 partial each); the last block
// to finish (semaphore) sums the 192 block results and writes the output.
// Deterministic: every sum has a fixed operand order; fence+atomic orders
// g_p2d writes before the final read.
__global__ void ssim_reduce(float* __restrict__ out) {
    int t = threadIdx.x;
    double s = (double)g_partials[blockIdx.x * 256 + t];
    #pragma unroll
    for (int o = 16; o; o >>= 1) s += __shfl_xor_sync(0xffffffffu, s, o);
    __shared__ double ws[8];
    if ((t & 31) == 0) ws[t >> 5] = s;
    __syncthreads();
    __shared__ bool is_last;
    if (t == 0) {
        double v = 0.0;
        #pragma unroll
        for (int w = 0; w < 8; w++) v += ws[w];
        g_p2d[blockIdx.x] = v;
        __threadfence();
        unsigned int n = atomicAdd(&g_sem, 1u);
        is_last = (n == RBLOCKS - 1);
    }
    __syncthreads();
    if (is_last && t < 32) {
        double v = 0.0;
        #pragma unroll
        for (int j = 0; j < RBLOCKS / 32; j++)    // 6 values per lane
            v += g_p2d[t + j * 32];
        #pragma unroll
        for (int o = 16; o; o >>= 1) v += __shfl_xor_sync(0xffffffffu, v, o);
        if (t == 0) {
            out[0] = (float)(v / (3.0 * 25165824.0));  // 3 maps * 32*3*512*512
            g_sem = 0;                                 // reset for next replay
        }
    }
}

extern "C" void kernel_launch(void* const* d_in, const int* in_sizes, int n_in,
                              void* d_out, int out_size) {
    const float* img1 = (const float*)d_in[0];
    const float* img2 = (const float*)d_in[1];
    constexpr int SMEM_BYTES = 8 * PLANE * (int)sizeof(float); // 22016
    cudaFuncSetAttribute(ssim_main, cudaFuncAttributeMaxDynamicSharedMemorySize, SMEM_BYTES);
    dim3 grid(NBX, NBY, NBZ);
    // Launch order (main, reduce, nop): with the 2 harness pre-launches and
    // period 3, global launch index 5 == ssim_main (ncu -s 5 -c 1 slot).
    ssim_main<<<grid, NTHREADS, SMEM_BYTES>>>(img1, img2);
    ssim_reduce<<<RBLOCKS, 256>>>((float*)d_out);
    ssim_nop<<<1, 32>>>();
}